// round 2
// baseline (speedup 1.0000x reference)
#include <cuda_runtime.h>

// ---------------------------------------------------------------------------
// GATv2 GraphEncoder: N=50000 nodes, E=800000 edges (+N self loops), 4 layers.
// Layers: (16,H4,D32,concat) (128,4,32,cat) (128,4,32,cat) (128,1,128,mean)
// All hidden widths are 128.
// ---------------------------------------------------------------------------

#define MAXN 50000
#define MAXE 800000

// scratch (device globals: allocation-free per harness rules)
__device__ float g_x [MAXN * 128];   // current node features (in-place across layers)
__device__ float g_xl[MAXN * 128];   // x @ Wl
__device__ float g_xr[MAXN * 128];   // x @ Wr
__device__ int   g_cnt[MAXN];
__device__ int   g_off[MAXN + 1];
__device__ int   g_cur[MAXN];
__device__ int   g_csr[MAXE + MAXN];
__device__ int   g_sums[128];

// ------------------------------ CSR build ---------------------------------

__global__ void k_init_cnt(int n) {
    int i = blockIdx.x * blockDim.x + threadIdx.x;
    if (i < n) g_cnt[i] = 1;   // self loop
}

__global__ void k_hist(const int* __restrict__ dst, int e) {
    int i = blockIdx.x * blockDim.x + threadIdx.x;
    if (i < e) atomicAdd(&g_cnt[dst[i]], 1);
}

__global__ void k_scan_blocks(int n) {
    __shared__ int s[1024];
    int t = threadIdx.x;
    int i = blockIdx.x * 1024 + t;
    int c = (i < n) ? g_cnt[i] : 0;
    s[t] = c;
    __syncthreads();
    #pragma unroll
    for (int o = 1; o < 1024; o <<= 1) {
        int v = (t >= o) ? s[t - o] : 0;
        __syncthreads();
        s[t] += v;
        __syncthreads();
    }
    if (i < n) g_off[i + 1] = s[t];
    if (t == 1023) g_sums[blockIdx.x] = s[1023];
}

__global__ void k_scan_sums(int nb) {
    if (blockIdx.x == 0 && threadIdx.x == 0) {
        int run = 0;
        for (int b = 0; b < nb; b++) {
            int v = g_sums[b];
            g_sums[b] = run;
            run += v;
        }
    }
}

__global__ void k_scan_add(int n) {
    int i = blockIdx.x * blockDim.x + threadIdx.x;
    if (i < n) g_off[i + 1] += g_sums[i >> 10];
    if (i == 0) g_off[0] = 0;
}

__global__ void k_init_cur(int n) {
    int i = blockIdx.x * blockDim.x + threadIdx.x;
    if (i < n) g_cur[i] = g_off[i];
}

__global__ void k_scatter(const int* __restrict__ src, const int* __restrict__ dst,
                          int e, int n) {
    int i = blockIdx.x * blockDim.x + threadIdx.x;
    if (i >= e + n) return;
    int s, d;
    if (i < e) { s = src[i]; d = dst[i]; }
    else       { s = i - e;  d = s; }
    int pos = atomicAdd(&g_cur[d], 1);
    g_csr[pos] = s;
}

// ------------------------------ GEMMs --------------------------------------
// xl = x @ Wl, xr = x @ Wr   (W: [in,128] row-major, out columns 128)
// block: (32,8), each thread computes 4 consecutive out columns of one row
// for both matrices. x row broadcast from shared; W via float4 (L1-resident).

__global__ void k_gemm0(const int* __restrict__ nt, const float* __restrict__ emb,
                        const float* __restrict__ Wl, const float* __restrict__ Wr,
                        int n) {
    __shared__ float xs[8][16];
    int tx = threadIdx.x, ty = threadIdx.y;
    int row = blockIdx.x * 8 + ty;
    if (tx < 16) xs[ty][tx] = (row < n) ? emb[nt[row] * 16 + tx] : 0.0f;
    __syncthreads();
    if (row >= n) return;
    const float4* Wl4 = (const float4*)Wl;
    const float4* Wr4 = (const float4*)Wr;
    float4 al = make_float4(0, 0, 0, 0), ar = make_float4(0, 0, 0, 0);
    #pragma unroll
    for (int k = 0; k < 16; k++) {
        float xv = xs[ty][k];
        float4 wl = Wl4[k * 32 + tx];
        float4 wr = Wr4[k * 32 + tx];
        al.x += xv * wl.x; al.y += xv * wl.y; al.z += xv * wl.z; al.w += xv * wl.w;
        ar.x += xv * wr.x; ar.y += xv * wr.y; ar.z += xv * wr.z; ar.w += xv * wr.w;
    }
    *(float4*)(g_xl + row * 128 + tx * 4) = al;
    *(float4*)(g_xr + row * 128 + tx * 4) = ar;
}

__global__ void k_gemm128(const float* __restrict__ Wl, const float* __restrict__ Wr,
                          int n) {
    __shared__ float xs[8][128];
    int tx = threadIdx.x, ty = threadIdx.y;
    int tid = ty * 32 + tx;
    int row0 = blockIdx.x * 8;
    {
        int r = tid >> 5;
        int c = (tid & 31) * 4;
        int row = row0 + r;
        float4 v = (row < n) ? *(const float4*)(g_x + row * 128 + c)
                             : make_float4(0, 0, 0, 0);
        *(float4*)&xs[r][c] = v;
    }
    __syncthreads();
    int row = row0 + ty;
    if (row >= n) return;
    const float4* Wl4 = (const float4*)Wl;
    const float4* Wr4 = (const float4*)Wr;
    float4 al = make_float4(0, 0, 0, 0), ar = make_float4(0, 0, 0, 0);
    #pragma unroll 8
    for (int k = 0; k < 128; k++) {
        float xv = xs[ty][k];
        float4 wl = Wl4[k * 32 + tx];
        float4 wr = Wr4[k * 32 + tx];
        al.x += xv * wl.x; al.y += xv * wl.y; al.z += xv * wl.z; al.w += xv * wl.w;
        ar.x += xv * wr.x; ar.y += xv * wr.y; ar.z += xv * wr.z; ar.w += xv * wr.w;
    }
    *(float4*)(g_xl + row * 128 + tx * 4) = al;
    *(float4*)(g_xr + row * 128 + tx * 4) = ar;
}

// --------------------------- edge aggregation ------------------------------
// one warp per destination node; online segment-softmax over incoming edges;
// fused bias + residual + LayerNorm + ReLU epilogue.

__device__ __forceinline__ float lrelu(float x) { return x > 0.0f ? x : 0.2f * x; }

__global__ void __launch_bounds__(256)
k_agg(const float* __restrict__ att, const float* __restrict__ bias,
      const float* __restrict__ lng, const float* __restrict__ lnb,
      int n, int segw, int use_res, int is_final, float* __restrict__ dout) {
    int gw = (blockIdx.x * blockDim.x + threadIdx.x) >> 5;
    int lane = threadIdx.x & 31;
    if (gw >= n) return;
    int v = gw;
    int base = v * 128 + lane * 4;

    float4 xrv = *(const float4*)(g_xr + base);
    float4 av  = *(const float4*)(att + lane * 4);

    float m = -1e30f, z = 0.0f;
    float a0 = 0.f, a1 = 0.f, a2 = 0.f, a3 = 0.f;

    int s0 = g_off[v], s1 = g_off[v + 1];
    for (int p = s0; p < s1; p++) {
        int s = g_csr[p];
        float4 xv = *(const float4*)(g_xl + s * 128 + lane * 4);
        float partial = lrelu(xv.x + xrv.x) * av.x + lrelu(xv.y + xrv.y) * av.y
                      + lrelu(xv.z + xrv.z) * av.z + lrelu(xv.w + xrv.w) * av.w;
        for (int o = segw >> 1; o > 0; o >>= 1)
            partial += __shfl_xor_sync(0xffffffffu, partial, o, segw);
        float l = partial;
        if (l > m) {
            float sc = __expf(m - l);
            a0 *= sc; a1 *= sc; a2 *= sc; a3 *= sc; z *= sc;
            m = l;
        }
        float pw = __expf(l - m);
        z += pw;
        a0 += pw * xv.x; a1 += pw * xv.y; a2 += pw * xv.z; a3 += pw * xv.w;
    }

    float inv = 1.0f / z;
    float4 bv = *(const float4*)(bias + lane * 4);
    float v0 = a0 * inv + bv.x;
    float v1 = a1 * inv + bv.y;
    float v2 = a2 * inv + bv.z;
    float v3 = a3 * inv + bv.w;
    if (use_res) {
        float4 rv = *(const float4*)(g_x + base);
        v0 += rv.x; v1 += rv.y; v2 += rv.z; v3 += rv.w;
    }

    // layernorm over 128 (warp allreduce)
    float sum = v0 + v1 + v2 + v3;
    #pragma unroll
    for (int o = 16; o > 0; o >>= 1) sum += __shfl_xor_sync(0xffffffffu, sum, o);
    float mean = sum * (1.0f / 128.0f);
    float d0 = v0 - mean, d1 = v1 - mean, d2 = v2 - mean, d3 = v3 - mean;
    float sq = d0 * d0 + d1 * d1 + d2 * d2 + d3 * d3;
    #pragma unroll
    for (int o = 16; o > 0; o >>= 1) sq += __shfl_xor_sync(0xffffffffu, sq, o);
    float rstd = rsqrtf(sq * (1.0f / 128.0f) + 1e-5f);

    float4 gv = *(const float4*)(lng + lane * 4);
    float4 lb = *(const float4*)(lnb + lane * 4);
    float4 o4;
    o4.x = fmaxf(d0 * rstd * gv.x + lb.x, 0.0f);
    o4.y = fmaxf(d1 * rstd * gv.y + lb.y, 0.0f);
    o4.z = fmaxf(d2 * rstd * gv.z + lb.z, 0.0f);
    o4.w = fmaxf(d3 * rstd * gv.w + lb.w, 0.0f);

    if (is_final) *(float4*)(dout + base) = o4;
    else          *(float4*)(g_x  + base) = o4;
}

// ------------------------------ launch -------------------------------------

extern "C" void kernel_launch(void* const* d_in, const int* in_sizes, int n_in,
                              void* d_out, int out_size) {
    const int*   node_types = (const int*)d_in[0];
    const int*   edge_index = (const int*)d_in[1];
    const float* emb        = (const float*)d_in[2];
    const float* Wl[4], *Wr[4], *att[4], *bias[4];
    for (int li = 0; li < 4; li++) {
        Wl[li]   = (const float*)d_in[3 + li * 4 + 0];
        Wr[li]   = (const float*)d_in[3 + li * 4 + 1];
        att[li]  = (const float*)d_in[3 + li * 4 + 2];
        bias[li] = (const float*)d_in[3 + li * 4 + 3];
    }
    const float* lng = (const float*)d_in[19];
    const float* lnb = (const float*)d_in[20];
    float* out = (float*)d_out;

    int n = in_sizes[0];
    int e = in_sizes[1] / 2;
    const int* esrc = edge_index;
    const int* edst = edge_index + e;

    // CSR by destination (includes self loops)
    k_init_cnt<<<(n + 255) / 256, 256>>>(n);
    k_hist<<<(e + 255) / 256, 256>>>(edst, e);
    int nb = (n + 1023) / 1024;
    k_scan_blocks<<<nb, 1024>>>(n);
    k_scan_sums<<<1, 32>>>(nb);
    k_scan_add<<<(n + 255) / 256, 256>>>(n);
    k_init_cur<<<(n + 255) / 256, 256>>>(n);
    k_scatter<<<(e + n + 255) / 256, 256>>>(esrc, edst, e, n);

    dim3 gt(32, 8);
    int gb = (n + 7) / 8;           // GEMM blocks (8 rows each)
    int ab = (n + 7) / 8;           // agg blocks  (8 warps each)

    // layer 0: in=16 (embedding gather), H=4 (segw 8), no residual
    k_gemm0<<<gb, gt>>>(node_types, emb, Wl[0], Wr[0], n);
    k_agg<<<ab, 256>>>(att[0], bias[0], lng + 0 * 128, lnb + 0 * 128,
                       n, 8, 0, 0, out);

    // layer 1: in=128, H=4, residual
    k_gemm128<<<gb, gt>>>(Wl[1], Wr[1], n);
    k_agg<<<ab, 256>>>(att[1], bias[1], lng + 1 * 128, lnb + 1 * 128,
                       n, 8, 1, 0, out);

    // layer 2: in=128, H=4, residual
    k_gemm128<<<gb, gt>>>(Wl[2], Wr[2], n);
    k_agg<<<ab, 256>>>(att[2], bias[2], lng + 2 * 128, lnb + 2 * 128,
                       n, 8, 1, 0, out);

    // layer 3: in=128, H=1 (segw 32), residual, writes d_out
    k_gemm128<<<gb, gt>>>(Wl[3], Wr[3], n);
    k_agg<<<ab, 256>>>(att[3], bias[3], lng + 3 * 128, lnb + 3 * 128,
                       n, 32, 1, 1, out);
}

// round 5
// speedup vs baseline: 1.6582x; 1.6582x over previous
#include <cuda_runtime.h>
#include <cuda_bf16.h>

// ---------------------------------------------------------------------------
// GATv2 GraphEncoder: N=50000 nodes, E=800000 edges (+N self loops), 4 layers.
// Layers: (16,H4,D32,concat) (128,4,32,cat) (128,4,32,cat) (128,1,128,mean)
// GEMMs (layers 1-3) run on tensor cores via split-bf16 (hi+lo) mma.sync,
// giving fp32-grade accuracy at tensor-core speed.
// ---------------------------------------------------------------------------

#define MAXN  50000
#define MAXNP 50176          // padded to multiple of 64 rows for mma tiles
#define MAXE  800000

// scratch (device globals: allocation-free per harness rules)
__device__ float g_x  [MAXN  * 128];  // current node features (residual)
__device__ float g_xl [MAXNP * 128];  // x @ Wl
__device__ float g_xr [MAXNP * 128];  // x @ Wr
__device__ __nv_bfloat16 g_xh [MAXNP * 128];  // bf16 hi of x
__device__ __nv_bfloat16 g_xlo[MAXNP * 128];  // bf16 lo of x
__device__ unsigned int g_wf[3][4][8192];     // frag-swizzled W: {Lhi,Llo,Rhi,Rlo}
__device__ int   g_cnt[MAXN];
__device__ int   g_off[MAXN + 1];
__device__ int   g_cur[MAXN];
__device__ int   g_csr[MAXE + MAXN];
__device__ int   g_sums[128];

// ------------------------------ CSR build ---------------------------------

__global__ void k_init_cnt(int n) {
    int i = blockIdx.x * blockDim.x + threadIdx.x;
    if (i < n) g_cnt[i] = 1;   // self loop
}

__global__ void k_hist(const int* __restrict__ dst, int e) {
    int i = blockIdx.x * blockDim.x + threadIdx.x;
    if (i < e) atomicAdd(&g_cnt[dst[i]], 1);
}

__global__ void k_scan_blocks(int n) {
    __shared__ int s[1024];
    int t = threadIdx.x;
    int i = blockIdx.x * 1024 + t;
    int c = (i < n) ? g_cnt[i] : 0;
    s[t] = c;
    __syncthreads();
    #pragma unroll
    for (int o = 1; o < 1024; o <<= 1) {
        int v = (t >= o) ? s[t - o] : 0;
        __syncthreads();
        s[t] += v;
        __syncthreads();
    }
    if (i < n) g_off[i + 1] = s[t];
    if (t == 1023) g_sums[blockIdx.x] = s[1023];
}

__global__ void k_scan_sums(int nb) {
    if (blockIdx.x == 0 && threadIdx.x == 0) {
        int run = 0;
        for (int b = 0; b < nb; b++) {
            int v = g_sums[b];
            g_sums[b] = run;
            run += v;
        }
    }
}

__global__ void k_scan_add(int n) {
    int i = blockIdx.x * blockDim.x + threadIdx.x;
    if (i < n) g_off[i + 1] += g_sums[i >> 10];
    if (i == 0) g_off[0] = 0;
}

__global__ void k_init_cur(int n) {
    int i = blockIdx.x * blockDim.x + threadIdx.x;
    if (i < n) g_cur[i] = g_off[i];
}

__global__ void k_scatter(const int* __restrict__ src, const int* __restrict__ dst,
                          int e, int n) {
    int i = blockIdx.x * blockDim.x + threadIdx.x;
    if (i >= e + n) return;
    int s, d;
    if (i < e) { s = src[i]; d = dst[i]; }
    else       { s = i - e;  d = s; }
    int pos = atomicAdd(&g_cur[d], 1);
    g_csr[pos] = s;
}

// ------------------------- weight frag preparation --------------------------
// Convert fp32 W[128(k) x 128(n)] into split-bf16 (hi/lo) packed directly in
// the mma.m16n8k16 B-fragment order: idx = ((ks*16 + n8)*32 + lane)*2 + {b0,b1}

__device__ __forceinline__ unsigned int pack2bf(float a, float b) {
    __nv_bfloat162 v = __floats2bfloat162_rn(a, b);
    return *reinterpret_cast<unsigned int*>(&v);
}

__global__ void k_prepW(const float* __restrict__ W0, const float* __restrict__ W1,
                        const float* __restrict__ W2, const float* __restrict__ W3,
                        const float* __restrict__ W4, const float* __restrict__ W5) {
    int tid = blockIdx.x * 256 + threadIdx.x;
    if (tid >= 6 * 8 * 16 * 32) return;
    int lane = tid & 31;
    int r = tid >> 5;
    int n8 = r & 15; r >>= 4;
    int ks = r & 7;  r >>= 3;
    int m = r;                       // 0..5: (layer,mat)
    const float* W;
    switch (m) { case 0: W = W0; break; case 1: W = W1; break;
                 case 2: W = W2; break; case 3: W = W3; break;
                 case 4: W = W4; break; default: W = W5; }
    int g = lane >> 2, t = lane & 3;
    int k0 = ks * 16, n0 = n8 * 8;
    float w00 = W[(k0 + 2 * t)     * 128 + n0 + g];
    float w01 = W[(k0 + 2 * t + 1) * 128 + n0 + g];
    float w10 = W[(k0 + 2 * t + 8) * 128 + n0 + g];
    float w11 = W[(k0 + 2 * t + 9) * 128 + n0 + g];
    float h00 = __bfloat162float(__float2bfloat16(w00));
    float h01 = __bfloat162float(__float2bfloat16(w01));
    float h10 = __bfloat162float(__float2bfloat16(w10));
    float h11 = __bfloat162float(__float2bfloat16(w11));
    int li = m >> 1, mat = m & 1;
    unsigned int* oh = g_wf[li][mat * 2 + 0];
    unsigned int* ol = g_wf[li][mat * 2 + 1];
    int idx = ((ks * 16 + n8) * 32 + lane) * 2;
    oh[idx]     = pack2bf(w00, w01);
    oh[idx + 1] = pack2bf(w10, w11);
    ol[idx]     = pack2bf(w00 - h00, w01 - h01);
    ol[idx + 1] = pack2bf(w10 - h10, w11 - h11);
}

// ------------------------------ GEMMs --------------------------------------

// layer 0: in=16, FFMA path (cheap), x from embedding gather
__global__ void k_gemm0(const int* __restrict__ nt, const float* __restrict__ emb,
                        const float* __restrict__ Wl, const float* __restrict__ Wr,
                        int n) {
    __shared__ float xs[8][16];
    int tx = threadIdx.x, ty = threadIdx.y;
    int row = blockIdx.x * 8 + ty;
    if (tx < 16) xs[ty][tx] = (row < n) ? emb[nt[row] * 16 + tx] : 0.0f;
    __syncthreads();
    if (row >= n) return;
    const float4* Wl4 = (const float4*)Wl;
    const float4* Wr4 = (const float4*)Wr;
    float4 al = make_float4(0, 0, 0, 0), ar = make_float4(0, 0, 0, 0);
    #pragma unroll
    for (int k = 0; k < 16; k++) {
        float xv = xs[ty][k];
        float4 wl = Wl4[k * 32 + tx];
        float4 wr = Wr4[k * 32 + tx];
        al.x += xv * wl.x; al.y += xv * wl.y; al.z += xv * wl.z; al.w += xv * wl.w;
        ar.x += xv * wr.x; ar.y += xv * wr.y; ar.z += xv * wr.z; ar.w += xv * wr.w;
    }
    *(float4*)(g_xl + row * 128 + tx * 4) = al;
    *(float4*)(g_xr + row * 128 + tx * 4) = ar;
}

// layers 1-3: tensor-core split-bf16. Block = 256 thr = 8 warps; warp (wr,wc)
// computes rows [blk*64 + wr*16, +16) x cols [wc*64, +64) of BOTH xl and xr.
#define MMA_BF16(D, A0, A1, A2, A3, B0, B1)                                   \
    asm volatile("mma.sync.aligned.m16n8k16.row.col.f32.bf16.bf16.f32 "       \
                 "{%0,%1,%2,%3}, {%4,%5,%6,%7}, {%8,%9}, {%0,%1,%2,%3};"      \
                 : "+f"(D[0]), "+f"(D[1]), "+f"(D[2]), "+f"(D[3])             \
                 : "r"(A0), "r"(A1), "r"(A2), "r"(A3), "r"(B0), "r"(B1))

__global__ void __launch_bounds__(256) k_gemm_t(int li) {
    int lane = threadIdx.x & 31, warp = threadIdx.x >> 5;
    int g = lane >> 2, t = lane & 3;
    int wr = warp >> 1, wc = warp & 1;
    int r0 = blockIdx.x * 64 + wr * 16;

    const unsigned int* XH  = (const unsigned int*)g_xh;
    const unsigned int* XLO = (const unsigned int*)g_xlo;
    const unsigned int* lh = g_wf[li][0];
    const unsigned int* ll = g_wf[li][1];
    const unsigned int* rh = g_wf[li][2];
    const unsigned int* rl = g_wf[li][3];

    float dl[8][4], dr[8][4];
    #pragma unroll
    for (int i = 0; i < 8; i++)
        #pragma unroll
        for (int j = 0; j < 4; j++) { dl[i][j] = 0.0f; dr[i][j] = 0.0f; }

    int rowA = (r0 + g) * 64;
    int rowB = (r0 + g + 8) * 64;

    #pragma unroll
    for (int ks = 0; ks < 8; ks++) {
        int kb = ks * 8 + t;
        unsigned int ah0 = XH[rowA + kb],     ah1 = XH[rowB + kb];
        unsigned int ah2 = XH[rowA + kb + 4], ah3 = XH[rowB + kb + 4];
        unsigned int al0 = XLO[rowA + kb],     al1 = XLO[rowB + kb];
        unsigned int al2 = XLO[rowA + kb + 4], al3 = XLO[rowB + kb + 4];
        #pragma unroll
        for (int n8 = 0; n8 < 8; n8++) {
            int nn = wc * 8 + n8;
            int bidx = ((ks * 16 + nn) * 32 + lane) * 2;
            uint2 bh = *(const uint2*)(lh + bidx);
            uint2 bl = *(const uint2*)(ll + bidx);
            MMA_BF16(dl[n8], ah0, ah1, ah2, ah3, bh.x, bh.y);
            MMA_BF16(dl[n8], ah0, ah1, ah2, ah3, bl.x, bl.y);
            MMA_BF16(dl[n8], al0, al1, al2, al3, bh.x, bh.y);
            uint2 ch = *(const uint2*)(rh + bidx);
            uint2 cl = *(const uint2*)(rl + bidx);
            MMA_BF16(dr[n8], ah0, ah1, ah2, ah3, ch.x, ch.y);
            MMA_BF16(dr[n8], ah0, ah1, ah2, ah3, cl.x, cl.y);
            MMA_BF16(dr[n8], al0, al1, al2, al3, ch.x, ch.y);
        }
    }

    #pragma unroll
    for (int n8 = 0; n8 < 8; n8++) {
        int c = (wc * 8 + n8) * 8 + 2 * t;
        *(float2*)&g_xl[(r0 + g)     * 128 + c] = make_float2(dl[n8][0], dl[n8][1]);
        *(float2*)&g_xl[(r0 + g + 8) * 128 + c] = make_float2(dl[n8][2], dl[n8][3]);
        *(float2*)&g_xr[(r0 + g)     * 128 + c] = make_float2(dr[n8][0], dr[n8][1]);
        *(float2*)&g_xr[(r0 + g + 8) * 128 + c] = make_float2(dr[n8][2], dr[n8][3]);
    }
}

// --------------------------- edge aggregation ------------------------------
// one warp per destination node; online segment-softmax over incoming edges;
// fused bias + residual + LayerNorm + ReLU epilogue; writes fp32 + bf16 hi/lo.

__device__ __forceinline__ float lrelu(float x) { return x > 0.0f ? x : 0.2f * x; }

__global__ void __launch_bounds__(256)
k_agg(const float* __restrict__ att, const float* __restrict__ bias,
      const float* __restrict__ lng, const float* __restrict__ lnb,
      int n, int segw, int use_res, int is_final, float* __restrict__ dout) {
    int gw = (blockIdx.x * blockDim.x + threadIdx.x) >> 5;
    int lane = threadIdx.x & 31;
    if (gw >= n) return;
    int v = gw;
    int base = v * 128 + lane * 4;

    float4 xrv = *(const float4*)(g_xr + base);
    float4 av  = *(const float4*)(att + lane * 4);

    float m = -1e30f, z = 0.0f;
    float a0 = 0.f, a1 = 0.f, a2 = 0.f, a3 = 0.f;

    const float4* XL = (const float4*)g_xl;
    int s0 = g_off[v], s1 = g_off[v + 1];

    // software-pipelined gather: next edge's row load issues before the
    // shfl/exp dependency chain of the current edge.
    int s = g_csr[s0];
    float4 xv = XL[s * 32 + lane];
    for (int p = s0; p < s1; p++) {
        float4 xc = xv;
        if (p + 1 < s1) {
            int sn = g_csr[p + 1];
            xv = XL[sn * 32 + lane];
        }
        float partial = lrelu(xc.x + xrv.x) * av.x + lrelu(xc.y + xrv.y) * av.y
                      + lrelu(xc.z + xrv.z) * av.z + lrelu(xc.w + xrv.w) * av.w;
        for (int o = segw >> 1; o > 0; o >>= 1)
            partial += __shfl_xor_sync(0xffffffffu, partial, o, segw);
        float l = partial;
        if (l > m) {
            float sc = __expf(m - l);
            a0 *= sc; a1 *= sc; a2 *= sc; a3 *= sc; z *= sc;
            m = l;
        }
        float pw = __expf(l - m);
        z += pw;
        a0 += pw * xc.x; a1 += pw * xc.y; a2 += pw * xc.z; a3 += pw * xc.w;
    }

    float inv = 1.0f / z;
    float4 bv = *(const float4*)(bias + lane * 4);
    float v0 = a0 * inv + bv.x;
    float v1 = a1 * inv + bv.y;
    float v2 = a2 * inv + bv.z;
    float v3 = a3 * inv + bv.w;
    if (use_res) {
        float4 rv = *(const float4*)(g_x + base);
        v0 += rv.x; v1 += rv.y; v2 += rv.z; v3 += rv.w;
    }

    // layernorm over 128 (warp allreduce)
    float sum = v0 + v1 + v2 + v3;
    #pragma unroll
    for (int o = 16; o > 0; o >>= 1) sum += __shfl_xor_sync(0xffffffffu, sum, o);
    float mean = sum * (1.0f / 128.0f);
    float d0 = v0 - mean, d1 = v1 - mean, d2 = v2 - mean, d3 = v3 - mean;
    float sq = d0 * d0 + d1 * d1 + d2 * d2 + d3 * d3;
    #pragma unroll
    for (int o = 16; o > 0; o >>= 1) sq += __shfl_xor_sync(0xffffffffu, sq, o);
    float rstd = rsqrtf(sq * (1.0f / 128.0f) + 1e-5f);

    float4 gv = *(const float4*)(lng + lane * 4);
    float4 lb = *(const float4*)(lnb + lane * 4);
    float4 o4;
    o4.x = fmaxf(d0 * rstd * gv.x + lb.x, 0.0f);
    o4.y = fmaxf(d1 * rstd * gv.y + lb.y, 0.0f);
    o4.z = fmaxf(d2 * rstd * gv.z + lb.z, 0.0f);
    o4.w = fmaxf(d3 * rstd * gv.w + lb.w, 0.0f);

    if (is_final) {
        *(float4*)(dout + base) = o4;
    } else {
        *(float4*)(g_x + base) = o4;                      // residual for next layer
        // split-bf16 for the next tensor-core GEMM
        float h0 = __bfloat162float(__float2bfloat16(o4.x));
        float h1 = __bfloat162float(__float2bfloat16(o4.y));
        float h2 = __bfloat162float(__float2bfloat16(o4.z));
        float h3 = __bfloat162float(__float2bfloat16(o4.w));
        unsigned int* XH  = (unsigned int*)g_xh;
        unsigned int* XLO = (unsigned int*)g_xlo;
        *(uint2*)&XH[v * 64 + lane * 2] =
            make_uint2(pack2bf(o4.x, o4.y), pack2bf(o4.z, o4.w));
        *(uint2*)&XLO[v * 64 + lane * 2] =
            make_uint2(pack2bf(o4.x - h0, o4.y - h1), pack2bf(o4.z - h2, o4.w - h3));
    }
}

// ------------------------------ launch -------------------------------------

extern "C" void kernel_launch(void* const* d_in, const int* in_sizes, int n_in,
                              void* d_out, int out_size) {
    const int*   node_types = (const int*)d_in[0];
    const int*   edge_index = (const int*)d_in[1];
    const float* emb        = (const float*)d_in[2];
    const float* Wl[4], *Wr[4], *att[4], *bias[4];
    for (int li = 0; li < 4; li++) {
        Wl[li]   = (const float*)d_in[3 + li * 4 + 0];
        Wr[li]   = (const float*)d_in[3 + li * 4 + 1];
        att[li]  = (const float*)d_in[3 + li * 4 + 2];
        bias[li] = (const float*)d_in[3 + li * 4 + 3];
    }
    const float* lng = (const float*)d_in[19];
    const float* lnb = (const float*)d_in[20];
    float* out = (float*)d_out;

    int n = in_sizes[0];
    int e = in_sizes[1] / 2;
    const int* esrc = edge_index;
    const int* edst = edge_index + e;

    // CSR by destination (includes self loops)
    k_init_cnt<<<(n + 255) / 256, 256>>>(n);
    k_hist<<<(e + 255) / 256, 256>>>(edst, e);
    int nb = (n + 1023) / 1024;
    k_scan_blocks<<<nb, 1024>>>(n);
    k_scan_sums<<<1, 32>>>(nb);
    k_scan_add<<<(n + 255) / 256, 256>>>(n);
    k_init_cur<<<(n + 255) / 256, 256>>>(n);
    k_scatter<<<(e + n + 255) / 256, 256>>>(esrc, edst, e, n);

    // weight fragments for tensor-core layers (1..3)
    k_prepW<<<96, 256>>>(Wl[1], Wr[1], Wl[2], Wr[2], Wl[3], Wr[3]);

    dim3 gt(32, 8);
    int gb  = (n + 7) / 8;           // gemm0 blocks (8 rows each)
    int ab  = (n + 7) / 8;           // agg blocks (8 warps each)
    int tb  = (n + 63) / 64;         // tensor GEMM blocks (64 rows each)

    // layer 0: in=16 (embedding gather), H=4 (segw 8), no residual
    k_gemm0<<<gb, gt>>>(node_types, emb, Wl[0], Wr[0], n);
    k_agg<<<ab, 256>>>(att[0], bias[0], lng + 0 * 128, lnb + 0 * 128,
                       n, 8, 0, 0, out);

    // layer 1: in=128, H=4, residual
    k_gemm_t<<<tb, 256>>>(0);
    k_agg<<<ab, 256>>>(att[1], bias[1], lng + 1 * 128, lnb + 1 * 128,
                       n, 8, 1, 0, out);

    // layer 2: in=128, H=4, residual
    k_gemm_t<<<tb, 256>>>(1);
    k_agg<<<ab, 256>>>(att[2], bias[2], lng + 2 * 128, lnb + 2 * 128,
                       n, 8, 1, 0, out);

    // layer 3: in=128, H=1 (segw 32), residual, writes d_out
    k_gemm_t<<<tb, 256>>>(2);
    k_agg<<<ab, 256>>>(att[3], bias[3], lng + 3 * 128, lnb + 3 * 128,
                       n, 32, 1, 1, out);
}

// round 8
// speedup vs baseline: 2.0469x; 1.2344x over previous
#include <cuda_runtime.h>
#include <cuda_bf16.h>

// ---------------------------------------------------------------------------
// GATv2 GraphEncoder: N=50000 nodes, E=800000 edges (+N self loops), 4 layers.
// Layers: (16,H4,D32,concat) (128,4,32,cat) (128,4,32,cat) (128,1,128,mean)
// GEMMs (layers 1-3): tensor cores, split-bf16 (hi+lo) mma.sync, fp32-grade.
// Aggregation: 1 warp/node, online segment-softmax, 2 edges per iteration.
// ---------------------------------------------------------------------------

#define MAXN  50000
#define MAXNP 50176          // padded to multiple of 64 rows for mma tiles
#define MAXE  800000

__device__ float g_x  [MAXN  * 128];  // current node features (residual)
__device__ float g_xl [MAXNP * 128];  // x @ Wl
__device__ float g_xr [MAXNP * 128];  // x @ Wr
__device__ __nv_bfloat16 g_xh [MAXNP * 128];  // bf16 hi of x
__device__ __nv_bfloat16 g_xlo[MAXNP * 128];  // bf16 lo of x
__device__ unsigned int g_wf[3][4][8192];     // frag-swizzled W: {Lhi,Llo,Rhi,Rlo}
__device__ int   g_cnt[MAXN];
__device__ int   g_off[MAXN + 1];
__device__ int   g_cur[MAXN + 1];
__device__ int   g_csr[MAXE + MAXN];
__device__ int   g_sums[128];

// ------------------------------ CSR build ---------------------------------

__global__ void k_hist(const int* __restrict__ dst, int e) {
    int i = blockIdx.x * blockDim.x + threadIdx.x;
    if (i < e) atomicAdd(&g_cnt[dst[i]], 1);
}

// inclusive scan within 1024-blocks; +1 folds the self loop in
__global__ void k_scan_blocks(int n) {
    __shared__ int s[1024];
    int t = threadIdx.x;
    int i = blockIdx.x * 1024 + t;
    int c = (i < n) ? g_cnt[i] + 1 : 0;
    s[t] = c;
    __syncthreads();
    #pragma unroll
    for (int o = 1; o < 1024; o <<= 1) {
        int v = (t >= o) ? s[t - o] : 0;
        __syncthreads();
        s[t] += v;
        __syncthreads();
    }
    if (i < n) g_off[i + 1] = s[t];
    if (t == 1023) g_sums[blockIdx.x] = s[1023];
}

// add cross-block prefix (computed per block from g_sums), finalize off + cur
__global__ void k_scan_finish(int n) {
    __shared__ int pre;
    int blk = (blockIdx.x * 256) >> 10;       // 256-thread blocks: blk uniform
    if (threadIdx.x == 0) {
        int r = 0;
        #pragma unroll 8
        for (int b = 0; b < blk; b++) r += g_sums[b];
        pre = r;
    }
    __syncthreads();
    int i = blockIdx.x * 256 + threadIdx.x;
    if (i < n) {
        int v = g_off[i + 1] + pre;
        g_off[i + 1] = v;
        g_cur[i + 1] = v;
    }
    if (i == 0) { g_off[0] = 0; g_cur[0] = 0; }
}

__global__ void k_scatter(const int* __restrict__ src, const int* __restrict__ dst,
                          int e, int n) {
    int i = blockIdx.x * blockDim.x + threadIdx.x;
    if (i >= e + n) return;
    int s, d;
    if (i < e) { s = src[i]; d = dst[i]; }
    else       { s = i - e;  d = s; }
    int pos = atomicAdd(&g_cur[d], 1);
    g_csr[pos] = s;
}

// ------------------------- weight frag preparation --------------------------

__device__ __forceinline__ unsigned int pack2bf(float a, float b) {
    __nv_bfloat162 v = __floats2bfloat162_rn(a, b);
    return *reinterpret_cast<unsigned int*>(&v);
}

__global__ void k_prepW(const float* __restrict__ W0, const float* __restrict__ W1,
                        const float* __restrict__ W2, const float* __restrict__ W3,
                        const float* __restrict__ W4, const float* __restrict__ W5) {
    int tid = blockIdx.x * 256 + threadIdx.x;
    if (tid >= 6 * 8 * 16 * 32) return;
    int lane = tid & 31;
    int r = tid >> 5;
    int n8 = r & 15; r >>= 4;
    int ks = r & 7;  r >>= 3;
    int m = r;
    const float* W;
    switch (m) { case 0: W = W0; break; case 1: W = W1; break;
                 case 2: W = W2; break; case 3: W = W3; break;
                 case 4: W = W4; break; default: W = W5; }
    int g = lane >> 2, t = lane & 3;
    int k0 = ks * 16, n0 = n8 * 8;
    float w00 = W[(k0 + 2 * t)     * 128 + n0 + g];
    float w01 = W[(k0 + 2 * t + 1) * 128 + n0 + g];
    float w10 = W[(k0 + 2 * t + 8) * 128 + n0 + g];
    float w11 = W[(k0 + 2 * t + 9) * 128 + n0 + g];
    float h00 = __bfloat162float(__float2bfloat16(w00));
    float h01 = __bfloat162float(__float2bfloat16(w01));
    float h10 = __bfloat162float(__float2bfloat16(w10));
    float h11 = __bfloat162float(__float2bfloat16(w11));
    int li = m >> 1, mat = m & 1;
    unsigned int* oh = g_wf[li][mat * 2 + 0];
    unsigned int* ol = g_wf[li][mat * 2 + 1];
    int idx = ((ks * 16 + n8) * 32 + lane) * 2;
    oh[idx]     = pack2bf(w00, w01);
    oh[idx + 1] = pack2bf(w10, w11);
    ol[idx]     = pack2bf(w00 - h00, w01 - h01);
    ol[idx + 1] = pack2bf(w10 - h10, w11 - h11);
}

// ------------------------------ GEMMs --------------------------------------

__global__ void k_gemm0(const int* __restrict__ nt, const float* __restrict__ emb,
                        const float* __restrict__ Wl, const float* __restrict__ Wr,
                        int n) {
    __shared__ float xs[8][16];
    int tx = threadIdx.x, ty = threadIdx.y;
    int row = blockIdx.x * 8 + ty;
    if (tx < 16) xs[ty][tx] = (row < n) ? emb[nt[row] * 16 + tx] : 0.0f;
    __syncthreads();
    if (row >= n) return;
    const float4* Wl4 = (const float4*)Wl;
    const float4* Wr4 = (const float4*)Wr;
    float4 al = make_float4(0, 0, 0, 0), ar = make_float4(0, 0, 0, 0);
    #pragma unroll
    for (int k = 0; k < 16; k++) {
        float xv = xs[ty][k];
        float4 wl = Wl4[k * 32 + tx];
        float4 wr = Wr4[k * 32 + tx];
        al.x += xv * wl.x; al.y += xv * wl.y; al.z += xv * wl.z; al.w += xv * wl.w;
        ar.x += xv * wr.x; ar.y += xv * wr.y; ar.z += xv * wr.z; ar.w += xv * wr.w;
    }
    *(float4*)(g_xl + row * 128 + tx * 4) = al;
    *(float4*)(g_xr + row * 128 + tx * 4) = ar;
}

#define MMA_BF16(D, A0, A1, A2, A3, B0, B1)                                   \
    asm volatile("mma.sync.aligned.m16n8k16.row.col.f32.bf16.bf16.f32 "       \
                 "{%0,%1,%2,%3}, {%4,%5,%6,%7}, {%8,%9}, {%0,%1,%2,%3};"      \
                 : "+f"(D[0]), "+f"(D[1]), "+f"(D[2]), "+f"(D[3])             \
                 : "r"(A0), "r"(A1), "r"(A2), "r"(A3), "r"(B0), "r"(B1))

__global__ void __launch_bounds__(256) k_gemm_t(int li) {
    int lane = threadIdx.x & 31, warp = threadIdx.x >> 5;
    int g = lane >> 2, t = lane & 3;
    int wr = warp >> 1, wc = warp & 1;
    int r0 = blockIdx.x * 64 + wr * 16;

    const unsigned int* XH  = (const unsigned int*)g_xh;
    const unsigned int* XLO = (const unsigned int*)g_xlo;
    const unsigned int* lh = g_wf[li][0];
    const unsigned int* ll = g_wf[li][1];
    const unsigned int* rh = g_wf[li][2];
    const unsigned int* rl = g_wf[li][3];

    float dl[8][4], dr[8][4];
    #pragma unroll
    for (int i = 0; i < 8; i++)
        #pragma unroll
        for (int j = 0; j < 4; j++) { dl[i][j] = 0.0f; dr[i][j] = 0.0f; }

    int rowA = (r0 + g) * 64;
    int rowB = (r0 + g + 8) * 64;

    #pragma unroll
    for (int ks = 0; ks < 8; ks++) {
        int kb = ks * 8 + t;
        unsigned int ah0 = __ldg(XH + rowA + kb),     ah1 = __ldg(XH + rowB + kb);
        unsigned int ah2 = __ldg(XH + rowA + kb + 4), ah3 = __ldg(XH + rowB + kb + 4);
        unsigned int al0 = __ldg(XLO + rowA + kb),     al1 = __ldg(XLO + rowB + kb);
        unsigned int al2 = __ldg(XLO + rowA + kb + 4), al3 = __ldg(XLO + rowB + kb + 4);
        #pragma unroll
        for (int n8 = 0; n8 < 8; n8++) {
            int nn = wc * 8 + n8;
            int bidx = ((ks * 16 + nn) * 32 + lane) * 2;
            uint2 bh = __ldg((const uint2*)(lh + bidx));
            uint2 bl = __ldg((const uint2*)(ll + bidx));
            MMA_BF16(dl[n8], ah0, ah1, ah2, ah3, bh.x, bh.y);
            MMA_BF16(dl[n8], ah0, ah1, ah2, ah3, bl.x, bl.y);
            MMA_BF16(dl[n8], al0, al1, al2, al3, bh.x, bh.y);
            uint2 ch = __ldg((const uint2*)(rh + bidx));
            uint2 cl = __ldg((const uint2*)(rl + bidx));
            MMA_BF16(dr[n8], ah0, ah1, ah2, ah3, ch.x, ch.y);
            MMA_BF16(dr[n8], ah0, ah1, ah2, ah3, cl.x, cl.y);
            MMA_BF16(dr[n8], al0, al1, al2, al3, ch.x, ch.y);
        }
    }

    #pragma unroll
    for (int n8 = 0; n8 < 8; n8++) {
        int c = (wc * 8 + n8) * 8 + 2 * t;
        *(float2*)&g_xl[(r0 + g)     * 128 + c] = make_float2(dl[n8][0], dl[n8][1]);
        *(float2*)&g_xl[(r0 + g + 8) * 128 + c] = make_float2(dl[n8][2], dl[n8][3]);
        *(float2*)&g_xr[(r0 + g)     * 128 + c] = make_float2(dr[n8][0], dr[n8][1]);
        *(float2*)&g_xr[(r0 + g + 8) * 128 + c] = make_float2(dr[n8][2], dr[n8][3]);
    }
}

// --------------------------- edge aggregation ------------------------------
// 1 warp/node; 2 edges per iteration (independent shfl chains interleave and
// the online-softmax rescale happens once per pair, branchless); prefetched
// gather; fused bias + residual + LayerNorm + ReLU (+ bf16 hi/lo) epilogue.

__device__ __forceinline__ float lrelu(float x) { return x > 0.0f ? x : 0.2f * x; }

template<int SEGW, int USE_RES, int IS_FINAL>
__global__ void __launch_bounds__(256)
k_agg(const float* __restrict__ att, const float* __restrict__ bias,
      const float* __restrict__ lng, const float* __restrict__ lnb,
      int n, float* __restrict__ dout) {
    int v = (blockIdx.x * blockDim.x + threadIdx.x) >> 5;
    int lane = threadIdx.x & 31;
    if (v >= n) return;
    int base = v * 128 + lane * 4;

    float4 xrv = *(const float4*)(g_xr + base);
    float4 av  = __ldg((const float4*)(att + lane * 4));

    float m = -1e30f, z = 0.0f;
    float a0 = 0.f, a1 = 0.f, a2 = 0.f, a3 = 0.f;

    const float4* __restrict__ XL = (const float4*)g_xl;
    const int* __restrict__ CSR = g_csr;
    int s0 = g_off[v], s1 = g_off[v + 1];

    // preload first pair
    int p = s0;
    int cA = CSR[p];
    int cB = (p + 1 < s1) ? CSR[p + 1] : cA;
    float4 xA = __ldg(XL + cA * 32 + lane);
    float4 xB = __ldg(XL + cB * 32 + lane);

    while (p < s1) {
        bool hasB = (p + 1 < s1);
        float4 a = xA, b = xB;
        int np = p + 2;
        if (np < s1) {                      // prefetch next pair
            int nA = CSR[np];
            int nB = (np + 1 < s1) ? CSR[np + 1] : nA;
            xA = __ldg(XL + nA * 32 + lane);
            xB = __ldg(XL + nB * 32 + lane);
        }

        float la = lrelu(a.x + xrv.x) * av.x + lrelu(a.y + xrv.y) * av.y
                 + lrelu(a.z + xrv.z) * av.z + lrelu(a.w + xrv.w) * av.w;
        float lb = lrelu(b.x + xrv.x) * av.x + lrelu(b.y + xrv.y) * av.y
                 + lrelu(b.z + xrv.z) * av.z + lrelu(b.w + xrv.w) * av.w;
        #pragma unroll
        for (int o = SEGW >> 1; o > 0; o >>= 1) {
            la += __shfl_xor_sync(0xffffffffu, la, o, SEGW);
            lb += __shfl_xor_sync(0xffffffffu, lb, o, SEGW);
        }
        if (!hasB) lb = -1e30f;

        float mn = fmaxf(m, fmaxf(la, lb));
        float sc = __expf(m - mn);          // == 1.0 when m unchanged
        float pa = __expf(la - mn);
        float pb = hasB ? __expf(lb - mn) : 0.0f;
        z  = z  * sc + pa + pb;
        a0 = a0 * sc + pa * a.x + pb * b.x;
        a1 = a1 * sc + pa * a.y + pb * b.y;
        a2 = a2 * sc + pa * a.z + pb * b.z;
        a3 = a3 * sc + pa * a.w + pb * b.w;
        m = mn;
        p = np;
    }

    float inv = 1.0f / z;
    float4 bv = __ldg((const float4*)(bias + lane * 4));
    float v0 = a0 * inv + bv.x;
    float v1 = a1 * inv + bv.y;
    float v2 = a2 * inv + bv.z;
    float v3 = a3 * inv + bv.w;
    if (USE_RES) {
        float4 rv = *(const float4*)(g_x + base);
        v0 += rv.x; v1 += rv.y; v2 += rv.z; v3 += rv.w;
    }

    float sum = v0 + v1 + v2 + v3;
    #pragma unroll
    for (int o = 16; o > 0; o >>= 1) sum += __shfl_xor_sync(0xffffffffu, sum, o);
    float mean = sum * (1.0f / 128.0f);
    float d0 = v0 - mean, d1 = v1 - mean, d2 = v2 - mean, d3 = v3 - mean;
    float sq = d0 * d0 + d1 * d1 + d2 * d2 + d3 * d3;
    #pragma unroll
    for (int o = 16; o > 0; o >>= 1) sq += __shfl_xor_sync(0xffffffffu, sq, o);
    float rstd = rsqrtf(sq * (1.0f / 128.0f) + 1e-5f);

    float4 gv = __ldg((const float4*)(lng + lane * 4));
    float4 lb4 = __ldg((const float4*)(lnb + lane * 4));
    float4 o4;
    o4.x = fmaxf(d0 * rstd * gv.x + lb4.x, 0.0f);
    o4.y = fmaxf(d1 * rstd * gv.y + lb4.y, 0.0f);
    o4.z = fmaxf(d2 * rstd * gv.z + lb4.z, 0.0f);
    o4.w = fmaxf(d3 * rstd * gv.w + lb4.w, 0.0f);

    if (IS_FINAL) {
        *(float4*)(dout + base) = o4;
    } else {
        *(float4*)(g_x + base) = o4;
        float h0 = __bfloat162float(__float2bfloat16(o4.x));
        float h1 = __bfloat162float(__float2bfloat16(o4.y));
        float h2 = __bfloat162float(__float2bfloat16(o4.z));
        float h3 = __bfloat162float(__float2bfloat16(o4.w));
        unsigned int* XH  = (unsigned int*)g_xh;
        unsigned int* XLO = (unsigned int*)g_xlo;
        *(uint2*)&XH[v * 64 + lane * 2] =
            make_uint2(pack2bf(o4.x, o4.y), pack2bf(o4.z, o4.w));
        *(uint2*)&XLO[v * 64 + lane * 2] =
            make_uint2(pack2bf(o4.x - h0, o4.y - h1), pack2bf(o4.z - h2, o4.w - h3));
    }
}

// ------------------------------ launch -------------------------------------

extern "C" void kernel_launch(void* const* d_in, const int* in_sizes, int n_in,
                              void* d_out, int out_size) {
    const int*   node_types = (const int*)d_in[0];
    const int*   edge_index = (const int*)d_in[1];
    const float* emb        = (const float*)d_in[2];
    const float* Wl[4], *Wr[4], *att[4], *bias[4];
    for (int li = 0; li < 4; li++) {
        Wl[li]   = (const float*)d_in[3 + li * 4 + 0];
        Wr[li]   = (const float*)d_in[3 + li * 4 + 1];
        att[li]  = (const float*)d_in[3 + li * 4 + 2];
        bias[li] = (const float*)d_in[3 + li * 4 + 3];
    }
    const float* lng = (const float*)d_in[19];
    const float* lnb = (const float*)d_in[20];
    float* out = (float*)d_out;

    int n = in_sizes[0];
    int e = in_sizes[1] / 2;
    const int* esrc = edge_index;
    const int* edst = edge_index + e;

    // CSR by destination (self loops folded into the scan's +1)
    void* cntp = nullptr;
    cudaGetSymbolAddress(&cntp, g_cnt);
    cudaMemsetAsync(cntp, 0, n * sizeof(int));
    k_hist<<<(e + 255) / 256, 256>>>(edst, e);                 // launch 0
    int nb = (n + 1023) / 1024;
    k_scan_blocks<<<nb, 1024>>>(n);                            // launch 1
    k_scan_finish<<<(n + 255) / 256, 256>>>(n);                // launch 2
    k_scatter<<<(e + n + 255) / 256, 256>>>(esrc, edst, e, n); // launch 3

    dim3 gt(32, 8);
    int gb  = (n + 7) / 8;
    int ab  = (n + 7) / 8;
    int tb  = (n + 63) / 64;

    // layer 0 (profiler slots 4/5 land on gemm0 / agg0)
    k_gemm0<<<gb, gt>>>(node_types, emb, Wl[0], Wr[0], n);     // launch 4
    k_agg<8, 0, 0><<<ab, 256>>>(att[0], bias[0], lng + 0 * 128, lnb + 0 * 128,
                                n, out);                       // launch 5

    k_prepW<<<96, 256>>>(Wl[1], Wr[1], Wl[2], Wr[2], Wl[3], Wr[3]);

    // layer 1
    k_gemm_t<<<tb, 256>>>(0);
    k_agg<8, 1, 0><<<ab, 256>>>(att[1], bias[1], lng + 1 * 128, lnb + 1 * 128,
                                n, out);

    // layer 2
    k_gemm_t<<<tb, 256>>>(1);
    k_agg<8, 1, 0><<<ab, 256>>>(att[2], bias[2], lng + 2 * 128, lnb + 2 * 128,
                                n, out);

    // layer 3
    k_gemm_t<<<tb, 256>>>(2);
    k_agg<32, 1, 1><<<ab, 256>>>(att[3], bias[3], lng + 3 * 128, lnb + 3 * 128,
                                 n, out);
}